// round 9
// baseline (speedup 1.0000x reference)
#include <cuda_runtime.h>
#include <cuda_fp16.h>
#include <cstdint>

#define Bn 32
#define Tn 1500
#define En 512
#define An 512
#define Cn 10
#define KW 201
#define On 512
#define NA_CHUNKS 4
#define TC_CHUNKS 15

#define MT 128
#define NTC 128
#define BK 32
#define NCHUNK 16
#define MTILES 375
#define NTILES 4

#define PITCH 80
#define TILEB (128 * PITCH)        // 10240
#define OFF_AL TILEB
#define OFF_BH (2 * TILEB)
#define OFF_BL (3 * TILEB)
#define STAGE_BYTES (4 * TILEB)    // 40960
#define SMEM_GEMM (2 * STAGE_BYTES)

// ---------------- scratch ----------------
__device__ float g_decproj[Bn * An];
__device__ float g_attc[Bn * Tn * Cn];
__device__ float g_epart[Bn * Tn * NA_CHUNKS];
__device__ float g_cpart[Bn * TC_CHUNKS * En];
__device__ __half g_bhi[An * En];   // [n][k]
__device__ __half g_blo[An * En];

// ---------------- helpers ----------------
__device__ __forceinline__ uint32_t smem_u32(const void* p) {
    uint32_t a;
    asm("{ .reg .u64 t; cvta.to.shared.u64 t, %1; cvt.u32.u64 %0, t; }" : "=r"(a) : "l"(p));
    return a;
}

// swizzled byte offset of 16B chunk c (0..3) in row `row` (80B pitch)
// rows r and r+8 share bank bases (20r mod 32); XOR by (r>>3)&3 decorrelates.
__device__ __forceinline__ uint32_t swz(uint32_t row, uint32_t c) {
    return row * PITCH + ((c ^ ((row >> 3) & 3)) << 4);
}

__device__ __forceinline__ void ldsm4(uint32_t& r0, uint32_t& r1, uint32_t& r2, uint32_t& r3,
                                      uint32_t addr) {
    asm volatile("ldmatrix.sync.aligned.m8n8.x4.shared.b16 {%0,%1,%2,%3}, [%4];"
                 : "=r"(r0), "=r"(r1), "=r"(r2), "=r"(r3) : "r"(addr));
}

__device__ __forceinline__ void mma16816(float* d, const uint32_t* a, const uint32_t* b) {
    asm volatile(
        "mma.sync.aligned.m16n8k16.row.col.f32.f16.f16.f32 "
        "{%0,%1,%2,%3}, {%4,%5,%6,%7}, {%8,%9}, {%0,%1,%2,%3};"
        : "+f"(d[0]), "+f"(d[1]), "+f"(d[2]), "+f"(d[3])
        : "r"(a[0]), "r"(a[1]), "r"(a[2]), "r"(a[3]), "r"(b[0]), "r"(b[1]));
}

__device__ __forceinline__ float fast_tanh(float x) {
    float e = __expf(2.0f * x);
    return 1.0f - 2.0f / (e + 1.0f);
}

__device__ __forceinline__ uint32_t h2u(__half2 h) {
    return *reinterpret_cast<uint32_t*>(&h);
}

__device__ __forceinline__ void split8(const float4& A, const float4& B,
                                       uint4& hi, uint4& lo) {
    __half2 h0 = __floats2half2_rn(A.x, A.y);
    __half2 h1 = __floats2half2_rn(A.z, A.w);
    __half2 h2 = __floats2half2_rn(B.x, B.y);
    __half2 h3 = __floats2half2_rn(B.z, B.w);
    float2 f0 = __half22float2(h0), f1 = __half22float2(h1);
    float2 f2 = __half22float2(h2), f3 = __half22float2(h3);
    __half2 l0 = __floats2half2_rn(A.x - f0.x, A.y - f0.y);
    __half2 l1 = __floats2half2_rn(A.z - f1.x, A.w - f1.y);
    __half2 l2 = __floats2half2_rn(B.x - f2.x, B.y - f2.y);
    __half2 l3 = __floats2half2_rn(B.z - f3.x, B.w - f3.y);
    hi.x = h2u(h0); hi.y = h2u(h1); hi.z = h2u(h2); hi.w = h2u(h3);
    lo.x = h2u(l0); lo.y = h2u(l1); lo.z = h2u(l2); lo.w = h2u(l3);
}

// ---------------- K_pre: fused prep_b + dec_proj + conv ----------------
__global__ void k_pre(const float* __restrict__ W_enc,
                      const float* __restrict__ dec_z,
                      const float* __restrict__ W_dec,
                      const float* __restrict__ b_enc,
                      const float* __restrict__ att_prev,
                      const float* __restrict__ conv_w) {
    __shared__ float sh[3648];
    int bx = blockIdx.x, tid = threadIdx.x;

    if (bx < 256) {
        float (*tile)[33] = (float(*)[33])sh;
        int n0 = (bx & 15) * 32, k0 = (bx >> 4) * 32;
        int tx = tid & 31, ty = tid >> 5;
        for (int i = ty; i < 32; i += 8)
            tile[i][tx] = W_enc[(size_t)(k0 + i) * An + n0 + tx];
        __syncthreads();
        for (int i = ty; i < 32; i += 8) {
            float v = tile[tx][i];
            __half hi = __float2half_rn(v);
            __half lo = __float2half_rn(v - __half2float(hi));
            g_bhi[(size_t)(n0 + i) * En + k0 + tx] = hi;
            g_blo[(size_t)(n0 + i) * En + k0 + tx] = lo;
        }
    } else if (bx < 320) {
        int bb = bx - 256;
        int b = bb >> 1;
        int a = (bb & 1) * 256 + tid;
        float* z = sh;
        for (int i = tid; i < 512; i += 256) z[i] = dec_z[b * 512 + i];
        __syncthreads();
        float acc = b_enc[a];
#pragma unroll 8
        for (int k = 0; k < 512; k++)
            acc = fmaf(z[k], W_dec[(size_t)k * An + a], acc);
        g_decproj[b * An + a] = acc;
    } else {
        int cb = bx - 320;
        int b = cb / 12, tb_ = cb % 12;
        int t0 = tb_ * 128;
        float* cw = sh;
        float* xs = sh + 2010;
        float* so = sh + 2338;
        for (int i = tid; i < Cn * KW; i += 256) cw[i] = conv_w[i];
        for (int i = tid; i < 128 + 200; i += 256) {
            int tt = t0 - 100 + i;
            xs[i] = (tt >= 0 && tt < Tn) ? att_prev[b * Tn + tt] : 0.0f;
        }
        __syncthreads();
        if (tid < 160) {
            int tg = tid & 15, c = tid >> 4;
            int tb = tg * 8;
            float acc[8] = {0, 0, 0, 0, 0, 0, 0, 0};
            float win[8];
#pragma unroll
            for (int j = 0; j < 8; j++) win[j] = xs[tb + j];
            const float* cwc = cw + c * KW;
#pragma unroll 8
            for (int h = 0; h < KW; h++) {
                float coef = cwc[h];
#pragma unroll
                for (int j = 0; j < 8; j++) acc[j] = fmaf(coef, win[j], acc[j]);
#pragma unroll
                for (int j = 0; j < 7; j++) win[j] = win[j + 1];
                win[7] = xs[tb + h + 8];
            }
#pragma unroll
            for (int j = 0; j < 8; j++) so[(tb + j) * Cn + c] = acc[j];
        }
        __syncthreads();
        int nvalid = Tn - t0;
        if (nvalid > 128) nvalid = 128;
        float* dst = g_attc + ((size_t)b * Tn + t0) * Cn;
        for (int i = tid; i < nvalid * Cn; i += 256) dst[i] = so[i];
    }
}

// ---------------- K3: HMMA fp16-split GEMM, CTA 128x128, swizzled -------
__global__ __launch_bounds__(256, 2) void k_gemm_e(
    const float* __restrict__ enc,
    const float* __restrict__ W_att,
    const float* __restrict__ gvec) {
    extern __shared__ char smem[];
    uint32_t sbase = smem_u32(smem);

    int tid = threadIdx.x;
    int wid = tid >> 5, lane = tid & 31;
    int wm = wid >> 1, wn = wid & 1;     // 4m x 2n warps, warp 32x64
    int ntile = blockIdx.x;
    int mtile = blockIdx.y;
    int row0 = mtile * MT;
    int n0 = ntile * NTC;

    float d[2][8][4];
#pragma unroll
    for (int mt = 0; mt < 2; mt++)
#pragma unroll
        for (int nt = 0; nt < 8; nt++)
#pragma unroll
            for (int r = 0; r < 4; r++) d[mt][nt][r] = 0.0f;

    // STS map: s selects K-half (16 fp16), r = row; chunks {2s, 2s+1}
    int s_half = tid >> 7;               // 0..1
    int r = tid & 127;
    const float* pa = enc + (size_t)(row0 + r) * En + s_half * 16;
    const __half* pbh = g_bhi + (size_t)(n0 + r) * En + s_half * 16;
    const __half* pbl = g_blo + (size_t)(n0 + r) * En + s_half * 16;
    uint32_t sw0 = swz((uint32_t)r, (uint32_t)(2 * s_half));
    uint32_t sw1 = swz((uint32_t)r, (uint32_t)(2 * s_half + 1));

    float4 aS0, aS1, aS2, aS3;
    uint4 bh0, bh1, bl0, bl1;
    auto load_regs = [&](int ck) {
        int ko = ck * BK;
        aS0 = *(const float4*)(pa + ko);
        aS1 = *(const float4*)(pa + ko + 4);
        aS2 = *(const float4*)(pa + ko + 8);
        aS3 = *(const float4*)(pa + ko + 12);
        bh0 = *(const uint4*)(pbh + ko);
        bh1 = *(const uint4*)(pbh + ko + 8);
        bl0 = *(const uint4*)(pbl + ko);
        bl1 = *(const uint4*)(pbl + ko + 8);
    };
    load_regs(0);

#pragma unroll 1
    for (int ck = 0; ck < NCHUNK; ck++) {
        int st = ck & 1;
        char* stn = smem + st * STAGE_BYTES;
        {
            uint4 hi, lo;
            split8(aS0, aS1, hi, lo);
            *(uint4*)(stn + sw0) = hi;
            *(uint4*)(stn + OFF_AL + sw0) = lo;
            split8(aS2, aS3, hi, lo);
            *(uint4*)(stn + sw1) = hi;
            *(uint4*)(stn + OFF_AL + sw1) = lo;
            *(uint4*)(stn + OFF_BH + sw0) = bh0;
            *(uint4*)(stn + OFF_BH + sw1) = bh1;
            *(uint4*)(stn + OFF_BL + sw0) = bl0;
            *(uint4*)(stn + OFF_BL + sw1) = bl1;
        }
        if (ck + 1 < NCHUNK) load_regs(ck + 1);
        __syncthreads();

        uint32_t stc = sbase + st * STAGE_BYTES;
#pragma unroll
        for (int kh = 0; kh < 2; kh++) {
            uint32_t aH[2][4], aL[2][4];
#pragma unroll
            for (int mt = 0; mt < 2; mt++) {
                uint32_t rowA = (uint32_t)(wm * 32 + mt * 16 + (lane & 15));
                uint32_t cA = (uint32_t)((kh << 1) + (lane >> 4));
                uint32_t off = swz(rowA, cA);
                ldsm4(aH[mt][0], aH[mt][1], aH[mt][2], aH[mt][3], stc + off);
                ldsm4(aL[mt][0], aL[mt][1], aL[mt][2], aL[mt][3], stc + OFF_AL + off);
            }
#pragma unroll
            for (int g = 0; g < 4; g++) {
                uint32_t rowB = (uint32_t)(wn * 64 + g * 16 + ((lane >> 4) << 3) + (lane & 7));
                uint32_t cB = (uint32_t)((kh << 1) + ((lane >> 3) & 1));
                uint32_t offB = swz(rowB, cB);
                uint32_t bh[4], bl[4];
                ldsm4(bh[0], bh[1], bh[2], bh[3], stc + OFF_BH + offB);
                ldsm4(bl[0], bl[1], bl[2], bl[3], stc + OFF_BL + offB);
#pragma unroll
                for (int mt = 0; mt < 2; mt++)
#pragma unroll
                    for (int f = 0; f < 2; f++) {
                        mma16816(d[mt][2 * g + f], aH[mt], &bh[2 * f]);
                        mma16816(d[mt][2 * g + f], aH[mt], &bl[2 * f]);
                        mma16816(d[mt][2 * g + f], aL[mt], &bh[2 * f]);
                    }
            }
        }
    }
    __syncthreads();

    // ---- epilogue (reuse smem) ----
    float* s_dec0 = (float*)smem;
    float* s_dec1 = s_dec0 + 128;
    float* s_gv   = s_dec1 + 128;
    float* s_wat  = s_gv + 128;           // [10][128]
    float* s_atc  = s_wat + Cn * 128;     // [128][10]
    float* s_e    = s_atc + 128 * Cn;     // [128][2]

    int b0 = row0 / Tn;
    int b1 = (row0 + MT - 1) / Tn;
    if (tid < 128) {
        s_dec0[tid] = g_decproj[b0 * An + n0 + tid];
        s_dec1[tid] = g_decproj[b1 * An + n0 + tid];
        s_gv[tid] = gvec[n0 + tid];
    }
    for (int i = tid; i < Cn * 128; i += 256)
        s_wat[i] = W_att[(i >> 7) * An + n0 + (i & 127)];
    for (int i = tid; i < 128 * Cn; i += 256) {
        int rr = i / Cn, c = i % Cn;
        int grow = row0 + rr;
        int b = grow / Tn, t = grow - b * Tn;
        s_atc[rr * Cn + c] = g_attc[((size_t)b * Tn + t) * Cn + c];
    }
    __syncthreads();

    int gid = lane >> 2, tid2 = lane & 3;
#pragma unroll
    for (int mt = 0; mt < 2; mt++) {
        int r0l = wm * 32 + mt * 16 + gid;
        int r1l = r0l + 8;
        int gb0 = (row0 + r0l) / Tn;
        int gb1 = (row0 + r1l) / Tn;
        const float* dec0 = (gb0 == b0) ? s_dec0 : s_dec1;
        const float* dec1 = (gb1 == b0) ? s_dec0 : s_dec1;
        float s0 = 0.0f, s1 = 0.0f;
#pragma unroll
        for (int nt = 0; nt < 8; nt++) {
            int n = wn * 64 + nt * 8 + tid2 * 2;
#pragma unroll
            for (int j = 0; j < 2; j++) {
                int nn = n + j;
                float v0 = d[mt][nt][j] + dec0[nn];
                float v1 = d[mt][nt][2 + j] + dec1[nn];
#pragma unroll
                for (int c = 0; c < Cn; c++) {
                    float w = s_wat[c * 128 + nn];
                    v0 = fmaf(s_atc[r0l * Cn + c], w, v0);
                    v1 = fmaf(s_atc[r1l * Cn + c], w, v1);
                }
                s0 = fmaf(fast_tanh(v0), s_gv[nn], s0);
                s1 = fmaf(fast_tanh(v1), s_gv[nn], s1);
            }
        }
        s0 += __shfl_xor_sync(0xffffffffu, s0, 1);
        s0 += __shfl_xor_sync(0xffffffffu, s0, 2);
        s1 += __shfl_xor_sync(0xffffffffu, s1, 1);
        s1 += __shfl_xor_sync(0xffffffffu, s1, 2);
        if (tid2 == 0) {
            s_e[r0l * 2 + wn] = s0;
            s_e[r1l * 2 + wn] = s1;
        }
    }
    __syncthreads();
    if (tid < 128) {
        float e = s_e[tid * 2 + 0] + s_e[tid * 2 + 1];
        int grow = row0 + tid;
        int b = grow / Tn, t = grow - b * Tn;
        g_epart[((size_t)b * Tn + t) * NA_CHUNKS + ntile] = e;
    }
}

// ---------------- K4: softmax ----------------
__global__ void k_softmax(float* __restrict__ w_out) {
    int b = blockIdx.x, tid = threadIdx.x;
    __shared__ float es[Tn];
    __shared__ float red[512];
    for (int t = tid; t < Tn; t += 512) {
        const float* p = &g_epart[((size_t)b * Tn + t) * NA_CHUNKS];
        es[t] = 2.0f * (p[0] + p[1] + p[2] + p[3]);
    }
    __syncthreads();
    float mx = -1e30f;
    for (int t = tid; t < Tn; t += 512) mx = fmaxf(mx, es[t]);
    red[tid] = mx;
    __syncthreads();
    for (int s = 256; s > 0; s >>= 1) {
        if (tid < s) red[tid] = fmaxf(red[tid], red[tid + s]);
        __syncthreads();
    }
    mx = red[0];
    __syncthreads();
    float sum = 0.0f;
    for (int t = tid; t < Tn; t += 512) {
        float ex = __expf(es[t] - mx);
        es[t] = ex;
        sum += ex;
    }
    red[tid] = sum;
    __syncthreads();
    for (int s = 256; s > 0; s >>= 1) {
        if (tid < s) red[tid] += red[tid + s];
        __syncthreads();
    }
    float inv = 1.0f / red[0];
    for (int t = tid; t < Tn; t += 512) w_out[b * Tn + t] = es[t] * inv;
}

// ---------------- K5: context partials (2 accumulators) ----------------
__global__ void k_ctx(const float* __restrict__ enc,
                      const float* __restrict__ w) {
    int b = blockIdx.y, tc = blockIdx.x, e = threadIdx.x;
    const float* encb = enc + (size_t)b * Tn * En;
    const float* wb = w + b * Tn;
    int t0 = tc * 100;
    float acc0 = 0.0f, acc1 = 0.0f;
#pragma unroll 4
    for (int t = t0; t < t0 + 100; t += 2) {
        acc0 = fmaf(wb[t], encb[(size_t)t * En + e], acc0);
        acc1 = fmaf(wb[t + 1], encb[(size_t)(t + 1) * En + e], acc1);
    }
    g_cpart[((size_t)b * TC_CHUNKS + tc) * En + e] = acc0 + acc1;
}

// ---------------- K6: out_c ----------------
__global__ void k_out(const float* __restrict__ W_o,
                      const float* __restrict__ b_o,
                      float* __restrict__ out_c) {
    int b = blockIdx.y;
    int o = blockIdx.x * 128 + threadIdx.x;
    __shared__ float cs[En];
    for (int e = threadIdx.x; e < En; e += 128) {
        float s = 0.0f;
#pragma unroll
        for (int ch = 0; ch < TC_CHUNKS; ch++)
            s += g_cpart[((size_t)b * TC_CHUNKS + ch) * En + e];
        cs[e] = s;
    }
    __syncthreads();
    float acc = b_o[o];
#pragma unroll 8
    for (int e = 0; e < En; e++)
        acc = fmaf(cs[e], W_o[(size_t)e * On + o], acc);
    out_c[(size_t)b * On + o] = acc;
}

// ---------------- launch ----------------
extern "C" void kernel_launch(void* const* d_in, const int* in_sizes, int n_in,
                              void* d_out, int out_size) {
    const float* enc      = (const float*)d_in[0];
    const float* dec_z    = (const float*)d_in[2];
    const float* att_prev = (const float*)d_in[3];
    const float* W_enc    = (const float*)d_in[4];
    const float* b_enc    = (const float*)d_in[5];
    const float* W_dec    = (const float*)d_in[6];
    const float* W_att    = (const float*)d_in[7];
    const float* conv_w   = (const float*)d_in[8];
    const float* gvec     = (const float*)d_in[9];
    const float* W_o      = (const float*)d_in[10];
    const float* b_o      = (const float*)d_in[11];

    float* out   = (float*)d_out;
    float* out_c = out;            // [B, O]
    float* out_w = out + Bn * On;  // [B, T]

    cudaFuncSetAttribute(k_gemm_e, cudaFuncAttributeMaxDynamicSharedMemorySize, SMEM_GEMM);

    k_pre<<<704, 256>>>(W_enc, dec_z, W_dec, b_enc, att_prev, conv_w);
    k_gemm_e<<<dim3(NTILES, MTILES), 256, SMEM_GEMM>>>(enc, W_att, gvec);
    k_softmax<<<Bn, 512>>>(out_w);
    k_ctx<<<dim3(TC_CHUNKS, Bn), 512>>>(enc, out_w);
    k_out<<<dim3(On / 128, Bn), 128>>>(W_o, b_o, out_c);
}

// round 10
// speedup vs baseline: 1.3783x; 1.3783x over previous
#include <cuda_runtime.h>
#include <cuda_fp16.h>
#include <cstdint>

#define Bn 32
#define Tn 1500
#define En 512
#define An 512
#define Cn 10
#define KW 201
#define On 512
#define NA_CHUNKS 8
#define TC_CHUNKS 30

#define MT 128
#define NTC 64
#define BK 32
#define NCHUNK 16
#define MTILES 375
#define NTILES 8

#define OFF_BH 10240
#define OFF_BL 15360
#define STAGE_BYTES 20480
#define SMEM_GEMM STAGE_BYTES

// ---------------- scratch ----------------
__device__ float g_decproj[Bn * An];
__device__ float g_attc[Bn * Tn * Cn];
__device__ float g_epart[Bn * Tn * NA_CHUNKS];
__device__ float g_cpart[Bn * TC_CHUNKS * En];
__device__ __half g_bhi[An * En];   // [n][k]
__device__ __half g_blo[An * En];

// ---------------- helpers ----------------
__device__ __forceinline__ uint32_t smem_u32(const void* p) {
    uint32_t a;
    asm("{ .reg .u64 t; cvta.to.shared.u64 t, %1; cvt.u32.u64 %0, t; }" : "=r"(a) : "l"(p));
    return a;
}

__device__ __forceinline__ void ldsm4(uint32_t& r0, uint32_t& r1, uint32_t& r2, uint32_t& r3,
                                      uint32_t addr) {
    asm volatile("ldmatrix.sync.aligned.m8n8.x4.shared.b16 {%0,%1,%2,%3}, [%4];"
                 : "=r"(r0), "=r"(r1), "=r"(r2), "=r"(r3) : "r"(addr));
}

__device__ __forceinline__ void mma16816(float* d, const uint32_t* a, const uint32_t* b) {
    asm volatile(
        "mma.sync.aligned.m16n8k16.row.col.f32.f16.f16.f32 "
        "{%0,%1,%2,%3}, {%4,%5,%6,%7}, {%8,%9}, {%0,%1,%2,%3};"
        : "+f"(d[0]), "+f"(d[1]), "+f"(d[2]), "+f"(d[3])
        : "r"(a[0]), "r"(a[1]), "r"(a[2]), "r"(a[3]), "r"(b[0]), "r"(b[1]));
}

__device__ __forceinline__ float fast_tanh(float x) {
    float e = __expf(2.0f * x);
    return 1.0f - 2.0f / (e + 1.0f);
}

__device__ __forceinline__ uint32_t h2u(__half2 h) {
    return *reinterpret_cast<uint32_t*>(&h);
}

// convert 8 fp32 -> hi fp16x8 only (A path: lo pass dropped)
__device__ __forceinline__ void cvt8(const float4& A, const float4& B, uint4& hi) {
    __half2 h0 = __floats2half2_rn(A.x, A.y);
    __half2 h1 = __floats2half2_rn(A.z, A.w);
    __half2 h2 = __floats2half2_rn(B.x, B.y);
    __half2 h3 = __floats2half2_rn(B.z, B.w);
    hi.x = h2u(h0); hi.y = h2u(h1); hi.z = h2u(h2); hi.w = h2u(h3);
}

// ---------------- K_pre: fused prep_b + dec_proj + conv ----------------
__global__ void k_pre(const float* __restrict__ W_enc,
                      const float* __restrict__ dec_z,
                      const float* __restrict__ W_dec,
                      const float* __restrict__ b_enc,
                      const float* __restrict__ att_prev,
                      const float* __restrict__ conv_w) {
    __shared__ float sh[3648];
    int bx = blockIdx.x, tid = threadIdx.x;

    if (bx < 256) {
        float (*tile)[33] = (float(*)[33])sh;
        int n0 = (bx & 15) * 32, k0 = (bx >> 4) * 32;
        int tx = tid & 31, ty = tid >> 5;
        for (int i = ty; i < 32; i += 8)
            tile[i][tx] = W_enc[(size_t)(k0 + i) * An + n0 + tx];
        __syncthreads();
        for (int i = ty; i < 32; i += 8) {
            float v = tile[tx][i];
            __half hi = __float2half_rn(v);
            __half lo = __float2half_rn(v - __half2float(hi));
            g_bhi[(size_t)(n0 + i) * En + k0 + tx] = hi;
            g_blo[(size_t)(n0 + i) * En + k0 + tx] = lo;
        }
    } else if (bx < 320) {
        int bb = bx - 256;
        int b = bb >> 1;
        int a = (bb & 1) * 256 + tid;
        float* z = sh;
        for (int i = tid; i < 512; i += 256) z[i] = dec_z[b * 512 + i];
        __syncthreads();
        float acc = b_enc[a];
#pragma unroll 8
        for (int k = 0; k < 512; k++)
            acc = fmaf(z[k], W_dec[(size_t)k * An + a], acc);
        g_decproj[b * An + a] = acc;
    } else {
        int cb = bx - 320;
        int b = cb / 12, tb_ = cb % 12;
        int t0 = tb_ * 128;
        float* cw = sh;
        float* xs = sh + 2010;
        float* so = sh + 2338;
        for (int i = tid; i < Cn * KW; i += 256) cw[i] = conv_w[i];
        for (int i = tid; i < 128 + 200; i += 256) {
            int tt = t0 - 100 + i;
            xs[i] = (tt >= 0 && tt < Tn) ? att_prev[b * Tn + tt] : 0.0f;
        }
        __syncthreads();
        if (tid < 160) {
            int tg = tid & 15, c = tid >> 4;
            int tb = tg * 8;
            float acc[8] = {0, 0, 0, 0, 0, 0, 0, 0};
            float win[8];
#pragma unroll
            for (int j = 0; j < 8; j++) win[j] = xs[tb + j];
            const float* cwc = cw + c * KW;
#pragma unroll 8
            for (int h = 0; h < KW; h++) {
                float coef = cwc[h];
#pragma unroll
                for (int j = 0; j < 8; j++) acc[j] = fmaf(coef, win[j], acc[j]);
#pragma unroll
                for (int j = 0; j < 7; j++) win[j] = win[j + 1];
                win[7] = xs[tb + h + 8];
            }
#pragma unroll
            for (int j = 0; j < 8; j++) so[(tb + j) * Cn + c] = acc[j];
        }
        __syncthreads();
        int nvalid = Tn - t0;
        if (nvalid > 128) nvalid = 128;
        float* dst = g_attc + ((size_t)b * Tn + t0) * Cn;
        for (int i = tid; i < nvalid * Cn; i += 256) dst[i] = so[i];
    }
}

// ---------------- K3: HMMA GEMM (R6 design, A-lo pass dropped) ----------
// CTA 128x64, 8 warps (4m x 2n), warp 32x32, single-buffer + reg prefetch.
__global__ __launch_bounds__(256, 2) void k_gemm_e(
    const float* __restrict__ enc,
    const float* __restrict__ W_att,
    const float* __restrict__ gvec) {
    extern __shared__ char smem[];
    uint32_t sbase = smem_u32(smem);

    int tid = threadIdx.x;
    int wid = tid >> 5, lane = tid & 31;
    int wm = wid >> 1, wn = wid & 1;
    int ntile = blockIdx.x;
    int mtile = blockIdx.y;
    int row0 = mtile * MT;
    int n0 = ntile * NTC;

    float d[2][4][4];
#pragma unroll
    for (int mt = 0; mt < 2; mt++)
#pragma unroll
        for (int nt = 0; nt < 4; nt++)
#pragma unroll
            for (int r = 0; r < 4; r++) d[mt][nt][r] = 0.0f;

    int lr = tid >> 2, lc = tid & 3;
    const float* pa0 = enc + (size_t)(row0 + lr) * En + lc * 8;
    const float* pa1 = pa0 + (size_t)64 * En;
    const __half* pbh = g_bhi + (size_t)(n0 + lr) * En + lc * 8;
    const __half* pbl = g_blo + (size_t)(n0 + lr) * En + lc * 8;
    uint32_t da0 = (uint32_t)(lr * 80 + lc * 16);
    uint32_t da1 = (uint32_t)((64 + lr) * 80 + lc * 16);

    float4 a0a, a0b, a1a, a1b;
    uint4 rbh, rbl;
    auto load_regs = [&](int ck) {
        int ko = ck * BK;
        a0a = *(const float4*)(pa0 + ko);
        a0b = *(const float4*)(pa0 + ko + 4);
        a1a = *(const float4*)(pa1 + ko);
        a1b = *(const float4*)(pa1 + ko + 4);
        rbh = *(const uint4*)(pbh + ko);
        rbl = *(const uint4*)(pbl + ko);
    };
    load_regs(0);

    uint32_t laneA = (uint32_t)((lane & 15) * 80 + (lane >> 4) * 16);
    uint32_t laneB = (uint32_t)(((((lane >> 4) << 3) + (lane & 7))) * 80 + ((lane >> 3) & 1) * 16);
    uint32_t warpA = (uint32_t)(wm * 32 * 80);
    uint32_t warpB = (uint32_t)(wn * 32 * 80);
    uint32_t aH_base = sbase + warpA + laneA;
    uint32_t bH_base = sbase + OFF_BH + warpB + laneB;
    uint32_t bL_base = sbase + OFF_BL + warpB + laneB;

#pragma unroll 1
    for (int ck = 0; ck < NCHUNK; ck++) {
        __syncthreads();   // previous MMA done reading smem
        uint4 hi;
        cvt8(a0a, a0b, hi);
        *(uint4*)(smem + da0) = hi;
        cvt8(a1a, a1b, hi);
        *(uint4*)(smem + da1) = hi;
        *(uint4*)(smem + OFF_BH + da0) = rbh;
        *(uint4*)(smem + OFF_BL + da0) = rbl;
        __syncthreads();
        if (ck + 1 < NCHUNK) load_regs(ck + 1);

#pragma unroll
        for (int kh = 0; kh < 2; kh++) {
            uint32_t ko = kh * 32;  // 16 halves
            uint32_t aH[2][4], bH[4][2], bL[4][2];
#pragma unroll
            for (int mt = 0; mt < 2; mt++)
                ldsm4(aH[mt][0], aH[mt][1], aH[mt][2], aH[mt][3],
                      aH_base + mt * (16 * 80) + ko);
#pragma unroll
            for (int np = 0; np < 2; np++) {
                ldsm4(bH[np * 2][0], bH[np * 2][1], bH[np * 2 + 1][0], bH[np * 2 + 1][1],
                      bH_base + np * (16 * 80) + ko);
                ldsm4(bL[np * 2][0], bL[np * 2][1], bL[np * 2 + 1][0], bL[np * 2 + 1][1],
                      bL_base + np * (16 * 80) + ko);
            }
#pragma unroll
            for (int mt = 0; mt < 2; mt++)
#pragma unroll
                for (int nt = 0; nt < 4; nt++) {
                    mma16816(d[mt][nt], aH[mt], bH[nt]);
                    mma16816(d[mt][nt], aH[mt], bL[nt]);
                }
        }
    }
    __syncthreads();

    // ---- epilogue (reuse smem) ----
    float* s_dec0 = (float*)smem;          // 64
    float* s_dec1 = s_dec0 + 64;           // 64
    float* s_gv   = s_dec1 + 64;           // 64
    float* s_wat  = s_gv + 64;             // [10][64]
    float* s_atc  = s_wat + Cn * 64;       // [128][10]
    float* s_e    = s_atc + 128 * Cn;      // [128][2]

    int b0 = row0 / Tn;
    int b1 = (row0 + MT - 1) / Tn;
    if (tid < 64) {
        s_dec0[tid] = g_decproj[b0 * An + n0 + tid];
        s_dec1[tid] = g_decproj[b1 * An + n0 + tid];
        s_gv[tid] = gvec[n0 + tid];
    }
    for (int i = tid; i < Cn * 64; i += 256)
        s_wat[i] = W_att[(i >> 6) * An + n0 + (i & 63)];
    for (int i = tid; i < 128 * Cn; i += 256) {
        int r = i / Cn, c = i % Cn;
        int grow = row0 + r;
        int b = grow / Tn, t = grow - b * Tn;
        s_atc[r * Cn + c] = g_attc[((size_t)b * Tn + t) * Cn + c];
    }
    __syncthreads();

    int gid = lane >> 2, tid2 = lane & 3;
#pragma unroll
    for (int mt = 0; mt < 2; mt++) {
        int r0l = wm * 32 + mt * 16 + gid;
        int r1l = r0l + 8;
        int gb0 = (row0 + r0l) / Tn;
        int gb1 = (row0 + r1l) / Tn;
        const float* dec0 = (gb0 == b0) ? s_dec0 : s_dec1;
        const float* dec1 = (gb1 == b0) ? s_dec0 : s_dec1;
        float s0 = 0.0f, s1 = 0.0f;
#pragma unroll
        for (int nt = 0; nt < 4; nt++) {
            int n = wn * 32 + nt * 8 + tid2 * 2;
#pragma unroll
            for (int j = 0; j < 2; j++) {
                int nn = n + j;
                float v0 = d[mt][nt][j] + dec0[nn];
                float v1 = d[mt][nt][2 + j] + dec1[nn];
#pragma unroll
                for (int c = 0; c < Cn; c++) {
                    float w = s_wat[c * 64 + nn];
                    v0 = fmaf(s_atc[r0l * Cn + c], w, v0);
                    v1 = fmaf(s_atc[r1l * Cn + c], w, v1);
                }
                s0 = fmaf(fast_tanh(v0), s_gv[nn], s0);
                s1 = fmaf(fast_tanh(v1), s_gv[nn], s1);
            }
        }
        s0 += __shfl_xor_sync(0xffffffffu, s0, 1);
        s0 += __shfl_xor_sync(0xffffffffu, s0, 2);
        s1 += __shfl_xor_sync(0xffffffffu, s1, 1);
        s1 += __shfl_xor_sync(0xffffffffu, s1, 2);
        if (tid2 == 0) {
            s_e[r0l * 2 + wn] = s0;
            s_e[r1l * 2 + wn] = s1;
        }
    }
    __syncthreads();
    if (tid < 128) {
        float e = s_e[tid * 2 + 0] + s_e[tid * 2 + 1];
        int grow = row0 + tid;
        int b = grow / Tn, t = grow - b * Tn;
        g_epart[((size_t)b * Tn + t) * NA_CHUNKS + ntile] = e;
    }
}

// ---------------- K4: softmax ----------------
__global__ void k_softmax(float* __restrict__ w_out) {
    int b = blockIdx.x, tid = threadIdx.x;
    __shared__ float es[Tn];
    __shared__ float red[512];
    for (int t = tid; t < Tn; t += 512) {
        const float* p = &g_epart[((size_t)b * Tn + t) * NA_CHUNKS];
        float s = 0.0f;
#pragma unroll
        for (int i = 0; i < NA_CHUNKS; i++) s += p[i];
        es[t] = 2.0f * s;
    }
    __syncthreads();
    float mx = -1e30f;
    for (int t = tid; t < Tn; t += 512) mx = fmaxf(mx, es[t]);
    red[tid] = mx;
    __syncthreads();
    for (int s = 256; s > 0; s >>= 1) {
        if (tid < s) red[tid] = fmaxf(red[tid], red[tid + s]);
        __syncthreads();
    }
    mx = red[0];
    __syncthreads();
    float sum = 0.0f;
    for (int t = tid; t < Tn; t += 512) {
        float ex = __expf(es[t] - mx);
        es[t] = ex;
        sum += ex;
    }
    red[tid] = sum;
    __syncthreads();
    for (int s = 256; s > 0; s >>= 1) {
        if (tid < s) red[tid] += red[tid + s];
        __syncthreads();
    }
    float inv = 1.0f / red[0];
    for (int t = tid; t < Tn; t += 512) w_out[b * Tn + t] = es[t] * inv;
}

// ---------------- K5: context partials (30 T-chunks of 50) -------------
__global__ void k_ctx(const float* __restrict__ enc,
                      const float* __restrict__ w) {
    int b = blockIdx.y, tc = blockIdx.x, e = threadIdx.x;
    const float* encb = enc + (size_t)b * Tn * En;
    const float* wb = w + b * Tn;
    int t0 = tc * 50;
    float acc0 = 0.0f, acc1 = 0.0f;
#pragma unroll 5
    for (int t = t0; t < t0 + 50; t += 2) {
        acc0 = fmaf(wb[t], encb[(size_t)t * En + e], acc0);
        acc1 = fmaf(wb[t + 1], encb[(size_t)(t + 1) * En + e], acc1);
    }
    g_cpart[((size_t)b * TC_CHUNKS + tc) * En + e] = acc0 + acc1;
}

// ---------------- K6: out_c ----------------
__global__ void k_out(const float* __restrict__ W_o,
                      const float* __restrict__ b_o,
                      float* __restrict__ out_c) {
    int b = blockIdx.y;
    int o = blockIdx.x * 128 + threadIdx.x;
    __shared__ float cs[En];
    for (int e = threadIdx.x; e < En; e += 128) {
        float s = 0.0f;
#pragma unroll
        for (int ch = 0; ch < TC_CHUNKS; ch++)
            s += g_cpart[((size_t)b * TC_CHUNKS + ch) * En + e];
        cs[e] = s;
    }
    __syncthreads();
    float acc = b_o[o];
#pragma unroll 8
    for (int e = 0; e < En; e++)
        acc = fmaf(cs[e], W_o[(size_t)e * On + o], acc);
    out_c[(size_t)b * On + o] = acc;
}

// ---------------- launch ----------------
extern "C" void kernel_launch(void* const* d_in, const int* in_sizes, int n_in,
                              void* d_out, int out_size) {
    const float* enc      = (const float*)d_in[0];
    const float* dec_z    = (const float*)d_in[2];
    const float* att_prev = (const float*)d_in[3];
    const float* W_enc    = (const float*)d_in[4];
    const float* b_enc    = (const float*)d_in[5];
    const float* W_dec    = (const float*)d_in[6];
    const float* W_att    = (const float*)d_in[7];
    const float* conv_w   = (const float*)d_in[8];
    const float* gvec     = (const float*)d_in[9];
    const float* W_o      = (const float*)d_in[10];
    const float* b_o      = (const float*)d_in[11];

    float* out   = (float*)d_out;
    float* out_c = out;            // [B, O]
    float* out_w = out + Bn * On;  // [B, T]

    cudaFuncSetAttribute(k_gemm_e, cudaFuncAttributeMaxDynamicSharedMemorySize, SMEM_GEMM);

    k_pre<<<704, 256>>>(W_enc, dec_z, W_dec, b_enc, att_prev, conv_w);
    k_gemm_e<<<dim3(NTILES, MTILES), 256, SMEM_GEMM>>>(enc, W_att, gvec);
    k_softmax<<<Bn, 512>>>(out_w);
    k_ctx<<<dim3(TC_CHUNKS, Bn), 512>>>(enc, out_w);
    k_out<<<dim3(On / 128, Bn), 128>>>(W_o, b_o, out_c);
}

// round 11
// speedup vs baseline: 1.5023x; 1.0899x over previous
#include <cuda_runtime.h>
#include <cuda_fp16.h>
#include <cstdint>

#define Bn 32
#define Tn 1500
#define En 512
#define An 512
#define Cn 10
#define KW 201
#define On 512
#define NA_CHUNKS 8
#define TC_CHUNKS 30

#define MT 128
#define NTC 64
#define BK 32
#define NCHUNK 16
#define MTILES 375
#define NTILES 8

#define OFF_BH 10240
#define STAGE_BYTES 15360
#define SMEM_GEMM STAGE_BYTES

// ---------------- scratch ----------------
__device__ float g_decproj[Bn * An];
__device__ float g_attc[Bn * Tn * Cn];
__device__ float g_epart[Bn * Tn * NA_CHUNKS];
__device__ float g_cpart[Bn * TC_CHUNKS * En];
__device__ __half g_bhi[An * En];   // [n][k]

// ---------------- helpers ----------------
__device__ __forceinline__ uint32_t smem_u32(const void* p) {
    uint32_t a;
    asm("{ .reg .u64 t; cvta.to.shared.u64 t, %1; cvt.u32.u64 %0, t; }" : "=r"(a) : "l"(p));
    return a;
}

__device__ __forceinline__ void ldsm4(uint32_t& r0, uint32_t& r1, uint32_t& r2, uint32_t& r3,
                                      uint32_t addr) {
    asm volatile("ldmatrix.sync.aligned.m8n8.x4.shared.b16 {%0,%1,%2,%3}, [%4];"
                 : "=r"(r0), "=r"(r1), "=r"(r2), "=r"(r3) : "r"(addr));
}

__device__ __forceinline__ void mma16816(float* d, const uint32_t* a, const uint32_t* b) {
    asm volatile(
        "mma.sync.aligned.m16n8k16.row.col.f32.f16.f16.f32 "
        "{%0,%1,%2,%3}, {%4,%5,%6,%7}, {%8,%9}, {%0,%1,%2,%3};"
        : "+f"(d[0]), "+f"(d[1]), "+f"(d[2]), "+f"(d[3])
        : "r"(a[0]), "r"(a[1]), "r"(a[2]), "r"(a[3]), "r"(b[0]), "r"(b[1]));
}

__device__ __forceinline__ float fast_tanh(float x) {
    float e = __expf(2.0f * x);
    return 1.0f - 2.0f / (e + 1.0f);
}

__device__ __forceinline__ uint32_t h2u(__half2 h) {
    return *reinterpret_cast<uint32_t*>(&h);
}

// convert 8 fp32 -> fp16x8
__device__ __forceinline__ void cvt8(const float4& A, const float4& B, uint4& hi) {
    __half2 h0 = __floats2half2_rn(A.x, A.y);
    __half2 h1 = __floats2half2_rn(A.z, A.w);
    __half2 h2 = __floats2half2_rn(B.x, B.y);
    __half2 h3 = __floats2half2_rn(B.z, B.w);
    hi.x = h2u(h0); hi.y = h2u(h1); hi.z = h2u(h2); hi.w = h2u(h3);
}

// ---------------- K_pre: fused prep_b + dec_proj + conv ----------------
__global__ void k_pre(const float* __restrict__ W_enc,
                      const float* __restrict__ dec_z,
                      const float* __restrict__ W_dec,
                      const float* __restrict__ b_enc,
                      const float* __restrict__ att_prev,
                      const float* __restrict__ conv_w) {
    __shared__ float sh[3648];
    int bx = blockIdx.x, tid = threadIdx.x;

    if (bx < 256) {
        float (*tile)[33] = (float(*)[33])sh;
        int n0 = (bx & 15) * 32, k0 = (bx >> 4) * 32;
        int tx = tid & 31, ty = tid >> 5;
        for (int i = ty; i < 32; i += 8)
            tile[i][tx] = W_enc[(size_t)(k0 + i) * An + n0 + tx];
        __syncthreads();
        for (int i = ty; i < 32; i += 8) {
            float v = tile[tx][i];
            g_bhi[(size_t)(n0 + i) * En + k0 + tx] = __float2half_rn(v);
        }
    } else if (bx < 320) {
        int bb = bx - 256;
        int b = bb >> 1;
        int a = (bb & 1) * 256 + tid;
        float* z = sh;
        for (int i = tid; i < 512; i += 256) z[i] = dec_z[b * 512 + i];
        __syncthreads();
        float acc = b_enc[a];
#pragma unroll 8
        for (int k = 0; k < 512; k++)
            acc = fmaf(z[k], W_dec[(size_t)k * An + a], acc);
        g_decproj[b * An + a] = acc;
    } else {
        int cb = bx - 320;
        int b = cb / 12, tb_ = cb % 12;
        int t0 = tb_ * 128;
        float* cw = sh;
        float* xs = sh + 2010;
        float* so = sh + 2338;
        for (int i = tid; i < Cn * KW; i += 256) cw[i] = conv_w[i];
        for (int i = tid; i < 128 + 200; i += 256) {
            int tt = t0 - 100 + i;
            xs[i] = (tt >= 0 && tt < Tn) ? att_prev[b * Tn + tt] : 0.0f;
        }
        __syncthreads();
        if (tid < 160) {
            int tg = tid & 15, c = tid >> 4;
            int tb = tg * 8;
            float acc[8] = {0, 0, 0, 0, 0, 0, 0, 0};
            float win[8];
#pragma unroll
            for (int j = 0; j < 8; j++) win[j] = xs[tb + j];
            const float* cwc = cw + c * KW;
#pragma unroll 8
            for (int h = 0; h < KW; h++) {
                float coef = cwc[h];
#pragma unroll
                for (int j = 0; j < 8; j++) acc[j] = fmaf(coef, win[j], acc[j]);
#pragma unroll
                for (int j = 0; j < 7; j++) win[j] = win[j + 1];
                win[7] = xs[tb + h + 8];
            }
#pragma unroll
            for (int j = 0; j < 8; j++) so[(tb + j) * Cn + c] = acc[j];
        }
        __syncthreads();
        int nvalid = Tn - t0;
        if (nvalid > 128) nvalid = 128;
        float* dst = g_attc + ((size_t)b * Tn + t0) * Cn;
        for (int i = tid; i < nvalid * Cn; i += 256) dst[i] = so[i];
    }
}

// ---------------- K3: HMMA fp16 GEMM (single pass) ----------------------
// CTA 128x64, 8 warps (4m x 2n), warp 32x32, single-buffer + reg prefetch.
__global__ __launch_bounds__(256, 2) void k_gemm_e(
    const float* __restrict__ enc,
    const float* __restrict__ W_att,
    const float* __restrict__ gvec) {
    extern __shared__ char smem[];
    uint32_t sbase = smem_u32(smem);

    int tid = threadIdx.x;
    int wid = tid >> 5, lane = tid & 31;
    int wm = wid >> 1, wn = wid & 1;
    int ntile = blockIdx.x;
    int mtile = blockIdx.y;
    int row0 = mtile * MT;
    int n0 = ntile * NTC;

    float d[2][4][4];
#pragma unroll
    for (int mt = 0; mt < 2; mt++)
#pragma unroll
        for (int nt = 0; nt < 4; nt++)
#pragma unroll
            for (int r = 0; r < 4; r++) d[mt][nt][r] = 0.0f;

    int lr = tid >> 2, lc = tid & 3;
    const float* pa0 = enc + (size_t)(row0 + lr) * En + lc * 8;
    const float* pa1 = pa0 + (size_t)64 * En;
    const __half* pbh = g_bhi + (size_t)(n0 + lr) * En + lc * 8;
    uint32_t da0 = (uint32_t)(lr * 80 + lc * 16);
    uint32_t da1 = (uint32_t)((64 + lr) * 80 + lc * 16);

    float4 a0a, a0b, a1a, a1b;
    uint4 rbh;
    auto load_regs = [&](int ck) {
        int ko = ck * BK;
        a0a = *(const float4*)(pa0 + ko);
        a0b = *(const float4*)(pa0 + ko + 4);
        a1a = *(const float4*)(pa1 + ko);
        a1b = *(const float4*)(pa1 + ko + 4);
        rbh = *(const uint4*)(pbh + ko);
    };
    load_regs(0);

    uint32_t laneA = (uint32_t)((lane & 15) * 80 + (lane >> 4) * 16);
    uint32_t laneB = (uint32_t)(((((lane >> 4) << 3) + (lane & 7))) * 80 + ((lane >> 3) & 1) * 16);
    uint32_t warpA = (uint32_t)(wm * 32 * 80);
    uint32_t warpB = (uint32_t)(wn * 32 * 80);
    uint32_t aH_base = sbase + warpA + laneA;
    uint32_t bH_base = sbase + OFF_BH + warpB + laneB;

#pragma unroll 1
    for (int ck = 0; ck < NCHUNK; ck++) {
        __syncthreads();   // previous MMA done reading smem
        uint4 hi;
        cvt8(a0a, a0b, hi);
        *(uint4*)(smem + da0) = hi;
        cvt8(a1a, a1b, hi);
        *(uint4*)(smem + da1) = hi;
        *(uint4*)(smem + OFF_BH + da0) = rbh;
        __syncthreads();
        if (ck + 1 < NCHUNK) load_regs(ck + 1);

#pragma unroll
        for (int kh = 0; kh < 2; kh++) {
            uint32_t ko = kh * 32;  // 16 halves
            uint32_t aH[2][4], bH[4][2];
#pragma unroll
            for (int mt = 0; mt < 2; mt++)
                ldsm4(aH[mt][0], aH[mt][1], aH[mt][2], aH[mt][3],
                      aH_base + mt * (16 * 80) + ko);
#pragma unroll
            for (int np = 0; np < 2; np++)
                ldsm4(bH[np * 2][0], bH[np * 2][1], bH[np * 2 + 1][0], bH[np * 2 + 1][1],
                      bH_base + np * (16 * 80) + ko);
#pragma unroll
            for (int mt = 0; mt < 2; mt++)
#pragma unroll
                for (int nt = 0; nt < 4; nt++)
                    mma16816(d[mt][nt], aH[mt], bH[nt]);
        }
    }
    __syncthreads();

    // ---- epilogue (reuse smem) ----
    float* s_dec0 = (float*)smem;          // 64
    float* s_dec1 = s_dec0 + 64;           // 64
    float* s_gv   = s_dec1 + 64;           // 64
    float* s_wat  = s_gv + 64;             // [10][64]
    float* s_atc  = s_wat + Cn * 64;       // [128][10]
    float* s_e    = s_atc + 128 * Cn;      // [128][2]

    int b0 = row0 / Tn;
    int b1 = (row0 + MT - 1) / Tn;
    if (tid < 64) {
        s_dec0[tid] = g_decproj[b0 * An + n0 + tid];
        s_dec1[tid] = g_decproj[b1 * An + n0 + tid];
        s_gv[tid] = gvec[n0 + tid];
    }
    for (int i = tid; i < Cn * 64; i += 256)
        s_wat[i] = W_att[(i >> 6) * An + n0 + (i & 63)];
    for (int i = tid; i < 128 * Cn; i += 256) {
        int r = i / Cn, c = i % Cn;
        int grow = row0 + r;
        int b = grow / Tn, t = grow - b * Tn;
        s_atc[r * Cn + c] = g_attc[((size_t)b * Tn + t) * Cn + c];
    }
    __syncthreads();

    int gid = lane >> 2, tid2 = lane & 3;
#pragma unroll
    for (int mt = 0; mt < 2; mt++) {
        int r0l = wm * 32 + mt * 16 + gid;
        int r1l = r0l + 8;
        int gb0 = (row0 + r0l) / Tn;
        int gb1 = (row0 + r1l) / Tn;
        const float* dec0 = (gb0 == b0) ? s_dec0 : s_dec1;
        const float* dec1 = (gb1 == b0) ? s_dec0 : s_dec1;
        float s0 = 0.0f, s1 = 0.0f;
#pragma unroll
        for (int nt = 0; nt < 4; nt++) {
            int n = wn * 32 + nt * 8 + tid2 * 2;
#pragma unroll
            for (int j = 0; j < 2; j++) {
                int nn = n + j;
                float v0 = d[mt][nt][j] + dec0[nn];
                float v1 = d[mt][nt][2 + j] + dec1[nn];
#pragma unroll
                for (int c = 0; c < Cn; c++) {
                    float w = s_wat[c * 64 + nn];
                    v0 = fmaf(s_atc[r0l * Cn + c], w, v0);
                    v1 = fmaf(s_atc[r1l * Cn + c], w, v1);
                }
                s0 = fmaf(fast_tanh(v0), s_gv[nn], s0);
                s1 = fmaf(fast_tanh(v1), s_gv[nn], s1);
            }
        }
        s0 += __shfl_xor_sync(0xffffffffu, s0, 1);
        s0 += __shfl_xor_sync(0xffffffffu, s0, 2);
        s1 += __shfl_xor_sync(0xffffffffu, s1, 1);
        s1 += __shfl_xor_sync(0xffffffffu, s1, 2);
        if (tid2 == 0) {
            s_e[r0l * 2 + wn] = s0;
            s_e[r1l * 2 + wn] = s1;
        }
    }
    __syncthreads();
    if (tid < 128) {
        float e = s_e[tid * 2 + 0] + s_e[tid * 2 + 1];
        int grow = row0 + tid;
        int b = grow / Tn, t = grow - b * Tn;
        g_epart[((size_t)b * Tn + t) * NA_CHUNKS + ntile] = e;
    }
}

// ---------------- K4: softmax ----------------
__global__ void k_softmax(float* __restrict__ w_out) {
    int b = blockIdx.x, tid = threadIdx.x;
    __shared__ float es[Tn];
    __shared__ float red[512];
    for (int t = tid; t < Tn; t += 512) {
        const float* p = &g_epart[((size_t)b * Tn + t) * NA_CHUNKS];
        float s = 0.0f;
#pragma unroll
        for (int i = 0; i < NA_CHUNKS; i++) s += p[i];
        es[t] = 2.0f * s;
    }
    __syncthreads();
    float mx = -1e30f;
    for (int t = tid; t < Tn; t += 512) mx = fmaxf(mx, es[t]);
    red[tid] = mx;
    __syncthreads();
    for (int s = 256; s > 0; s >>= 1) {
        if (tid < s) red[tid] = fmaxf(red[tid], red[tid + s]);
        __syncthreads();
    }
    mx = red[0];
    __syncthreads();
    float sum = 0.0f;
    for (int t = tid; t < Tn; t += 512) {
        float ex = __expf(es[t] - mx);
        es[t] = ex;
        sum += ex;
    }
    red[tid] = sum;
    __syncthreads();
    for (int s = 256; s > 0; s >>= 1) {
        if (tid < s) red[tid] += red[tid + s];
        __syncthreads();
    }
    float inv = 1.0f / red[0];
    for (int t = tid; t < Tn; t += 512) w_out[b * Tn + t] = es[t] * inv;
}

// ---------------- K5: context partials ----------------
__global__ void k_ctx(const float* __restrict__ enc,
                      const float* __restrict__ w) {
    int b = blockIdx.y, tc = blockIdx.x, e = threadIdx.x;
    const float* encb = enc + (size_t)b * Tn * En;
    const float* wb = w + b * Tn;
    int t0 = tc * 50;
    float acc0 = 0.0f, acc1 = 0.0f;
#pragma unroll 5
    for (int t = t0; t < t0 + 50; t += 2) {
        acc0 = fmaf(wb[t], encb[(size_t)t * En + e], acc0);
        acc1 = fmaf(wb[t + 1], encb[(size_t)(t + 1) * En + e], acc1);
    }
    g_cpart[((size_t)b * TC_CHUNKS + tc) * En + e] = acc0 + acc1;
}

// ---------------- K6: out_c ----------------
__global__ void k_out(const float* __restrict__ W_o,
                      const float* __restrict__ b_o,
                      float* __restrict__ out_c) {
    int b = blockIdx.y;
    int o = blockIdx.x * 128 + threadIdx.x;
    __shared__ float cs[En];
    for (int e = threadIdx.x; e < En; e += 128) {
        float s = 0.0f;
#pragma unroll
        for (int ch = 0; ch < TC_CHUNKS; ch++)
            s += g_cpart[((size_t)b * TC_CHUNKS + ch) * En + e];
        cs[e] = s;
    }
    __syncthreads();
    float acc = b_o[o];
#pragma unroll 8
    for (int e = 0; e < En; e++)
        acc = fmaf(cs[e], W_o[(size_t)e * On + o], acc);
    out_c[(size_t)b * On + o] = acc;
}

// ---------------- launch ----------------
extern "C" void kernel_launch(void* const* d_in, const int* in_sizes, int n_in,
                              void* d_out, int out_size) {
    const float* enc      = (const float*)d_in[0];
    const float* dec_z    = (const float*)d_in[2];
    const float* att_prev = (const float*)d_in[3];
    const float* W_enc    = (const float*)d_in[4];
    const float* b_enc    = (const float*)d_in[5];
    const float* W_dec    = (const float*)d_in[6];
    const float* W_att    = (const float*)d_in[7];
    const float* conv_w   = (const float*)d_in[8];
    const float* gvec     = (const float*)d_in[9];
    const float* W_o      = (const float*)d_in[10];
    const float* b_o      = (const float*)d_in[11];

    float* out   = (float*)d_out;
    float* out_c = out;            // [B, O]
    float* out_w = out + Bn * On;  // [B, T]

    cudaFuncSetAttribute(k_gemm_e, cudaFuncAttributeMaxDynamicSharedMemorySize, SMEM_GEMM);

    k_pre<<<704, 256>>>(W_enc, dec_z, W_dec, b_enc, att_prev, conv_w);
    k_gemm_e<<<dim3(NTILES, MTILES), 256, SMEM_GEMM>>>(enc, W_att, gvec);
    k_softmax<<<Bn, 512>>>(out_w);
    k_ctx<<<dim3(TC_CHUNKS, Bn), 512>>>(enc, out_w);
    k_out<<<dim3(On / 128, Bn), 128>>>(W_o, b_o, out_c);
}

// round 12
// speedup vs baseline: 1.6087x; 1.0708x over previous
#include <cuda_runtime.h>
#include <cuda_fp16.h>
#include <cstdint>

#define Bn 32
#define Tn 1500
#define En 512
#define An 512
#define Cn 10
#define KW 201
#define On 512
#define NA_CHUNKS 8
#define TC_CHUNKS 15

#define MT 128
#define NTC 64
#define BK 32
#define NCHUNK 16
#define MTILES 375
#define NTILES 8

#define OFF_BH 10240
#define STAGE_BYTES 15360
#define SMEM_GEMM (2 * STAGE_BYTES)

// ---------------- scratch ----------------
__device__ float g_decproj[Bn * An];
__device__ float g_attc[Bn * Tn * Cn];
__device__ float g_epart[Bn * Tn * NA_CHUNKS];
__device__ float g_cpart[Bn * TC_CHUNKS * En];
__device__ __half g_bhi[An * En];   // [n][k]

// ---------------- helpers ----------------
__device__ __forceinline__ uint32_t smem_u32(const void* p) {
    uint32_t a;
    asm("{ .reg .u64 t; cvta.to.shared.u64 t, %1; cvt.u32.u64 %0, t; }" : "=r"(a) : "l"(p));
    return a;
}

__device__ __forceinline__ void ldsm4(uint32_t& r0, uint32_t& r1, uint32_t& r2, uint32_t& r3,
                                      uint32_t addr) {
    asm volatile("ldmatrix.sync.aligned.m8n8.x4.shared.b16 {%0,%1,%2,%3}, [%4];"
                 : "=r"(r0), "=r"(r1), "=r"(r2), "=r"(r3) : "r"(addr));
}

__device__ __forceinline__ void mma16816(float* d, const uint32_t* a, const uint32_t* b) {
    asm volatile(
        "mma.sync.aligned.m16n8k16.row.col.f32.f16.f16.f32 "
        "{%0,%1,%2,%3}, {%4,%5,%6,%7}, {%8,%9}, {%0,%1,%2,%3};"
        : "+f"(d[0]), "+f"(d[1]), "+f"(d[2]), "+f"(d[3])
        : "r"(a[0]), "r"(a[1]), "r"(a[2]), "r"(a[3]), "r"(b[0]), "r"(b[1]));
}

__device__ __forceinline__ float fast_tanh(float x) {
    float e = __expf(2.0f * x);
    return 1.0f - 2.0f / (e + 1.0f);
}

__device__ __forceinline__ uint32_t h2u(__half2 h) {
    return *reinterpret_cast<uint32_t*>(&h);
}

// convert 8 fp32 -> fp16x8
__device__ __forceinline__ void cvt8(const float4& A, const float4& B, uint4& hi) {
    __half2 h0 = __floats2half2_rn(A.x, A.y);
    __half2 h1 = __floats2half2_rn(A.z, A.w);
    __half2 h2 = __floats2half2_rn(B.x, B.y);
    __half2 h3 = __floats2half2_rn(B.z, B.w);
    hi.x = h2u(h0); hi.y = h2u(h1); hi.z = h2u(h2); hi.w = h2u(h3);
}

// ---------------- K_pre: fused prep_b + dec_proj + conv ----------------
__global__ void k_pre(const float* __restrict__ W_enc,
                      const float* __restrict__ dec_z,
                      const float* __restrict__ W_dec,
                      const float* __restrict__ b_enc,
                      const float* __restrict__ att_prev,
                      const float* __restrict__ conv_w) {
    __shared__ float sh[3648];
    int bx = blockIdx.x, tid = threadIdx.x;

    if (bx < 256) {
        float (*tile)[33] = (float(*)[33])sh;
        int n0 = (bx & 15) * 32, k0 = (bx >> 4) * 32;
        int tx = tid & 31, ty = tid >> 5;
        for (int i = ty; i < 32; i += 8)
            tile[i][tx] = W_enc[(size_t)(k0 + i) * An + n0 + tx];
        __syncthreads();
        for (int i = ty; i < 32; i += 8) {
            float v = tile[tx][i];
            g_bhi[(size_t)(n0 + i) * En + k0 + tx] = __float2half_rn(v);
        }
    } else if (bx < 320) {
        int bb = bx - 256;
        int b = bb >> 1;
        int a = (bb & 1) * 256 + tid;
        float* z = sh;
        for (int i = tid; i < 512; i += 256) z[i] = dec_z[b * 512 + i];
        __syncthreads();
        float acc = b_enc[a];
#pragma unroll 8
        for (int k = 0; k < 512; k++)
            acc = fmaf(z[k], W_dec[(size_t)k * An + a], acc);
        g_decproj[b * An + a] = acc;
    } else {
        int cb = bx - 320;
        int b = cb / 12, tb_ = cb % 12;
        int t0 = tb_ * 128;
        float* cw = sh;
        float* xs = sh + 2010;
        float* so = sh + 2338;
        for (int i = tid; i < Cn * KW; i += 256) cw[i] = conv_w[i];
        for (int i = tid; i < 128 + 200; i += 256) {
            int tt = t0 - 100 + i;
            xs[i] = (tt >= 0 && tt < Tn) ? att_prev[b * Tn + tt] : 0.0f;
        }
        __syncthreads();
        if (tid < 160) {
            int tg = tid & 15, c = tid >> 4;
            int tb = tg * 8;
            float acc[8] = {0, 0, 0, 0, 0, 0, 0, 0};
            float win[8];
#pragma unroll
            for (int j = 0; j < 8; j++) win[j] = xs[tb + j];
            const float* cwc = cw + c * KW;
#pragma unroll 8
            for (int h = 0; h < KW; h++) {
                float coef = cwc[h];
#pragma unroll
                for (int j = 0; j < 8; j++) acc[j] = fmaf(coef, win[j], acc[j]);
#pragma unroll
                for (int j = 0; j < 7; j++) win[j] = win[j + 1];
                win[7] = xs[tb + h + 8];
            }
#pragma unroll
            for (int j = 0; j < 8; j++) so[(tb + j) * Cn + c] = acc[j];
        }
        __syncthreads();
        int nvalid = Tn - t0;
        if (nvalid > 128) nvalid = 128;
        float* dst = g_attc + ((size_t)b * Tn + t0) * Cn;
        for (int i = tid; i < nvalid * Cn; i += 256) dst[i] = so[i];
    }
}

// ---------------- K3: HMMA fp16 GEMM, double-buffered, 1 sync/chunk -----
// CTA 128x64, 8 warps (4m x 2n), warp 32x32.
__global__ __launch_bounds__(256, 2) void k_gemm_e(
    const float* __restrict__ enc,
    const float* __restrict__ W_att,
    const float* __restrict__ gvec) {
    extern __shared__ char smem[];
    uint32_t sbase = smem_u32(smem);

    int tid = threadIdx.x;
    int wid = tid >> 5, lane = tid & 31;
    int wm = wid >> 1, wn = wid & 1;
    int ntile = blockIdx.x;
    int mtile = blockIdx.y;
    int row0 = mtile * MT;
    int n0 = ntile * NTC;

    float d[2][4][4];
#pragma unroll
    for (int mt = 0; mt < 2; mt++)
#pragma unroll
        for (int nt = 0; nt < 4; nt++)
#pragma unroll
            for (int r = 0; r < 4; r++) d[mt][nt][r] = 0.0f;

    int lr = tid >> 2, lc = tid & 3;
    const float* pa0 = enc + (size_t)(row0 + lr) * En + lc * 8;
    const float* pa1 = pa0 + (size_t)64 * En;
    const __half* pbh = g_bhi + (size_t)(n0 + lr) * En + lc * 8;
    uint32_t da0 = (uint32_t)(lr * 80 + lc * 16);
    uint32_t da1 = (uint32_t)((64 + lr) * 80 + lc * 16);

    float4 a0a, a0b, a1a, a1b;
    uint4 rbh;
    auto load_regs = [&](int ck) {
        int ko = ck * BK;
        a0a = *(const float4*)(pa0 + ko);
        a0b = *(const float4*)(pa0 + ko + 4);
        a1a = *(const float4*)(pa1 + ko);
        a1b = *(const float4*)(pa1 + ko + 4);
        rbh = *(const uint4*)(pbh + ko);
    };
    auto store_stage = [&](char* stg) {
        uint4 hi;
        cvt8(a0a, a0b, hi);
        *(uint4*)(stg + da0) = hi;
        cvt8(a1a, a1b, hi);
        *(uint4*)(stg + da1) = hi;
        *(uint4*)(stg + OFF_BH + da0) = rbh;
    };

    uint32_t laneA = (uint32_t)((lane & 15) * 80 + (lane >> 4) * 16);
    uint32_t laneB = (uint32_t)(((((lane >> 4) << 3) + (lane & 7))) * 80 + ((lane >> 3) & 1) * 16);
    uint32_t warpA = (uint32_t)(wm * 32 * 80);
    uint32_t warpB = (uint32_t)(wn * 32 * 80);
    uint32_t aH_base = sbase + warpA + laneA;
    uint32_t bH_base = sbase + OFF_BH + warpB + laneB;

    // prologue: chunk 0 -> stage 0; prefetch chunk 1 into regs
    load_regs(0);
    store_stage(smem);
    load_regs(1);
    __syncthreads();

#pragma unroll 1
    for (int ck = 0; ck < NCHUNK; ck++) {
        int s = ck & 1;
        uint32_t so = (uint32_t)(s * STAGE_BYTES);

        // MMA on stage s
#pragma unroll
        for (int kh = 0; kh < 2; kh++) {
            uint32_t ko = so + kh * 32;
            uint32_t aH[2][4], bH[4][2];
#pragma unroll
            for (int mt = 0; mt < 2; mt++)
                ldsm4(aH[mt][0], aH[mt][1], aH[mt][2], aH[mt][3],
                      aH_base + mt * (16 * 80) + ko);
#pragma unroll
            for (int np = 0; np < 2; np++)
                ldsm4(bH[np * 2][0], bH[np * 2][1], bH[np * 2 + 1][0], bH[np * 2 + 1][1],
                      bH_base + np * (16 * 80) + ko);
#pragma unroll
            for (int mt = 0; mt < 2; mt++)
#pragma unroll
                for (int nt = 0; nt < 4; nt++)
                    mma16816(d[mt][nt], aH[mt], bH[nt]);
        }

        // stage regs (chunk ck+1) -> buffer s^1; prefetch chunk ck+2
        if (ck + 1 < NCHUNK) {
            store_stage(smem + (s ^ 1) * STAGE_BYTES);
            if (ck + 2 < NCHUNK) load_regs(ck + 2);
        }
        __syncthreads();
    }

    // ---- epilogue (reuse smem) ----
    float* s_dec0 = (float*)smem;          // 64
    float* s_dec1 = s_dec0 + 64;           // 64
    float* s_gv   = s_dec1 + 64;           // 64
    float* s_wat  = s_gv + 64;             // [10][64]
    float* s_atc  = s_wat + Cn * 64;       // [128][10]
    float* s_e    = s_atc + 128 * Cn;      // [128][2]

    int b0 = row0 / Tn;
    int b1 = (row0 + MT - 1) / Tn;
    if (tid < 64) {
        s_dec0[tid] = g_decproj[b0 * An + n0 + tid];
        s_dec1[tid] = g_decproj[b1 * An + n0 + tid];
        s_gv[tid] = gvec[n0 + tid];
    }
    for (int i = tid; i < Cn * 64; i += 256)
        s_wat[i] = W_att[(i >> 6) * An + n0 + (i & 63)];
    for (int i = tid; i < 128 * Cn; i += 256) {
        int r = i / Cn, c = i % Cn;
        int grow = row0 + r;
        int b = grow / Tn, t = grow - b * Tn;
        s_atc[r * Cn + c] = g_attc[((size_t)b * Tn + t) * Cn + c];
    }
    __syncthreads();

    int gid = lane >> 2, tid2 = lane & 3;
#pragma unroll
    for (int mt = 0; mt < 2; mt++) {
        int r0l = wm * 32 + mt * 16 + gid;
        int r1l = r0l + 8;
        int gb0 = (row0 + r0l) / Tn;
        int gb1 = (row0 + r1l) / Tn;
        const float* dec0 = (gb0 == b0) ? s_dec0 : s_dec1;
        const float* dec1 = (gb1 == b0) ? s_dec0 : s_dec1;
        float s0 = 0.0f, s1 = 0.0f;
#pragma unroll
        for (int nt = 0; nt < 4; nt++) {
            int n = wn * 32 + nt * 8 + tid2 * 2;
#pragma unroll
            for (int j = 0; j < 2; j++) {
                int nn = n + j;
                float v0 = d[mt][nt][j] + dec0[nn];
                float v1 = d[mt][nt][2 + j] + dec1[nn];
#pragma unroll
                for (int c = 0; c < Cn; c++) {
                    float w = s_wat[c * 64 + nn];
                    v0 = fmaf(s_atc[r0l * Cn + c], w, v0);
                    v1 = fmaf(s_atc[r1l * Cn + c], w, v1);
                }
                s0 = fmaf(fast_tanh(v0), s_gv[nn], s0);
                s1 = fmaf(fast_tanh(v1), s_gv[nn], s1);
            }
        }
        s0 += __shfl_xor_sync(0xffffffffu, s0, 1);
        s0 += __shfl_xor_sync(0xffffffffu, s0, 2);
        s1 += __shfl_xor_sync(0xffffffffu, s1, 1);
        s1 += __shfl_xor_sync(0xffffffffu, s1, 2);
        if (tid2 == 0) {
            s_e[r0l * 2 + wn] = s0;
            s_e[r1l * 2 + wn] = s1;
        }
    }
    __syncthreads();
    if (tid < 128) {
        float e = s_e[tid * 2 + 0] + s_e[tid * 2 + 1];
        int grow = row0 + tid;
        int b = grow / Tn, t = grow - b * Tn;
        g_epart[((size_t)b * Tn + t) * NA_CHUNKS + ntile] = e;
    }
}

// ---------------- K4: softmax ----------------
__global__ void k_softmax(float* __restrict__ w_out) {
    int b = blockIdx.x, tid = threadIdx.x;
    __shared__ float es[Tn];
    __shared__ float red[512];
    for (int t = tid; t < Tn; t += 512) {
        const float* p = &g_epart[((size_t)b * Tn + t) * NA_CHUNKS];
        float s = 0.0f;
#pragma unroll
        for (int i = 0; i < NA_CHUNKS; i++) s += p[i];
        es[t] = 2.0f * s;
    }
    __syncthreads();
    float mx = -1e30f;
    for (int t = tid; t < Tn; t += 512) mx = fmaxf(mx, es[t]);
    red[tid] = mx;
    __syncthreads();
    for (int s = 256; s > 0; s >>= 1) {
        if (tid < s) red[tid] = fmaxf(red[tid], red[tid + s]);
        __syncthreads();
    }
    mx = red[0];
    __syncthreads();
    float sum = 0.0f;
    for (int t = tid; t < Tn; t += 512) {
        float ex = __expf(es[t] - mx);
        es[t] = ex;
        sum += ex;
    }
    red[tid] = sum;
    __syncthreads();
    for (int s = 256; s > 0; s >>= 1) {
        if (tid < s) red[tid] += red[tid + s];
        __syncthreads();
    }
    float inv = 1.0f / red[0];
    for (int t = tid; t < Tn; t += 512) w_out[b * Tn + t] = es[t] * inv;
}

// ---------------- K5: context partials (15 chunks, 4 accumulators) -----
__global__ void k_ctx(const float* __restrict__ enc,
                      const float* __restrict__ w) {
    int b = blockIdx.y, tc = blockIdx.x, e = threadIdx.x;
    const float* encb = enc + (size_t)b * Tn * En;
    const float* wb = w + b * Tn;
    int t0 = tc * 100;
    float acc0 = 0.0f, acc1 = 0.0f, acc2 = 0.0f, acc3 = 0.0f;
#pragma unroll 5
    for (int t = t0; t < t0 + 100; t += 4) {
        acc0 = fmaf(wb[t],     encb[(size_t)t * En + e], acc0);
        acc1 = fmaf(wb[t + 1], encb[(size_t)(t + 1) * En + e], acc1);
        acc2 = fmaf(wb[t + 2], encb[(size_t)(t + 2) * En + e], acc2);
        acc3 = fmaf(wb[t + 3], encb[(size_t)(t + 3) * En + e], acc3);
    }
    g_cpart[((size_t)b * TC_CHUNKS + tc) * En + e] = (acc0 + acc1) + (acc2 + acc3);
}

// ---------------- K6: out_c ----------------
__global__ void k_out(const float* __restrict__ W_o,
                      const float* __restrict__ b_o,
                      float* __restrict__ out_c) {
    int b = blockIdx.y;
    int o = blockIdx.x * 128 + threadIdx.x;
    __shared__ float cs[En];
    for (int e = threadIdx.x; e < En; e += 128) {
        float s = 0.0f;
#pragma unroll
        for (int ch = 0; ch < TC_CHUNKS; ch++)
            s += g_cpart[((size_t)b * TC_CHUNKS + ch) * En + e];
        cs[e] = s;
    }
    __syncthreads();
    float acc = b_o[o];
#pragma unroll 8
    for (int e = 0; e < En; e++)
        acc = fmaf(cs[e], W_o[(size_t)e * On + o], acc);
    out_c[(size_t)b * On + o] = acc;
}

// ---------------- launch ----------------
extern "C" void kernel_launch(void* const* d_in, const int* in_sizes, int n_in,
                              void* d_out, int out_size) {
    const float* enc      = (const float*)d_in[0];
    const float* dec_z    = (const float*)d_in[2];
    const float* att_prev = (const float*)d_in[3];
    const float* W_enc    = (const float*)d_in[4];
    const float* b_enc    = (const float*)d_in[5];
    const float* W_dec    = (const float*)d_in[6];
    const float* W_att    = (const float*)d_in[7];
    const float* conv_w   = (const float*)d_in[8];
    const float* gvec     = (const float*)d_in[9];
    const float* W_o      = (const float*)d_in[10];
    const float* b_o      = (const float*)d_in[11];

    float* out   = (float*)d_out;
    float* out_c = out;            // [B, O]
    float* out_w = out + Bn * On;  // [B, T]

    cudaFuncSetAttribute(k_gemm_e, cudaFuncAttributeMaxDynamicSharedMemorySize, SMEM_GEMM);

    k_pre<<<704, 256>>>(W_enc, dec_z, W_dec, b_enc, att_prev, conv_w);
    k_gemm_e<<<dim3(NTILES, MTILES), 256, SMEM_GEMM>>>(enc, W_att, gvec);
    k_softmax<<<Bn, 512>>>(out_w);
    k_ctx<<<dim3(TC_CHUNKS, Bn), 512>>>(enc, out_w);
    k_out<<<dim3(On / 128, Bn), 128>>>(W_o, b_o, out_c);
}